// round 13
// baseline (speedup 1.0000x reference)
#include <cuda_runtime.h>
#include <cuda_bf16.h>
#include <cuda_fp16.h>
#include <cstdint>

// LightGCN via pull-based CSR gather, fp16 intermediates.
// deg = clamp(segsum(w by dst), 1); norm = deg^-1/2
// repeat 2x: h = segsum((h*norm)[src] * w, by dst) * norm
// out = mean(h0, h1, h2) -- assembled in the final gather.
//
// hist uses ONE packed 64-bit atomic: low 40 bits fixed-point(2^28) weighted
// degree, high 24 bits edge count (also yields each edge's rank).
// Gather: 16 lanes per node (uint2 = 4 fp16 dims per lane), unroll-8.

#define NN     100000
#define EE     1600000
#define SCAN_B 256
#define NB_MAX 512                        // >= ceil(NN/SCAN_B) = 391
#define FXS    268435456.0f               // 2^28
#define CNT_SH 40

__device__ unsigned long long g_packed[NN];  // zero at load; re-zeroed per launch
__device__ float    g_norm[NN];
__device__ int      g_rowptr[NN + 1];
__device__ unsigned short g_rank[EE];
__device__ int      g_bsum[NB_MAX];
__device__ float2   g_edge[EE];              // .x = bits(src), .y = w
__device__ uint2    g_ha[(size_t)NN * 16];   // layer-1 input (h0*norm), fp16
__device__ uint2    g_hb[(size_t)NN * 16];   // layer-2 input (h1*norm), fp16

// ---------------- CSR build ----------------

// one 64-bit atomic: weighted degree (fixed-point) + count (rank via return)
__global__ void k_hist(const float* __restrict__ w,
                       const int* __restrict__ dst, int e) {
    int i = blockIdx.x * blockDim.x + threadIdx.x;
    if (i >= e) return;
    int d = dst[i];
    unsigned long long fx =
        (unsigned long long)__float2uint_rn(w[i] * FXS) | (1ull << CNT_SH);
    unsigned long long old = atomicAdd(&g_packed[d], fx);
    g_rank[i] = (unsigned short)(old >> CNT_SH);
}

// per-block (256-node) exclusive scan of count -> rowptr(local); totals -> bsum
__global__ void k_scanA(int n) {
    __shared__ int sh[8];
    int i = blockIdx.x * SCAN_B + threadIdx.x;
    int lane = threadIdx.x & 31, wid = threadIdx.x >> 5;
    int v = (i < n) ? (int)(g_packed[i] >> CNT_SH) : 0;
    int x = v;
    #pragma unroll
    for (int o = 1; o < 32; o <<= 1) {
        int y = __shfl_up_sync(0xffffffffu, x, o);
        if (lane >= o) x += y;
    }
    if (lane == 31) sh[wid] = x;
    __syncthreads();
    if (threadIdx.x == 0) {
        int acc = 0;
        #pragma unroll
        for (int k = 0; k < 8; k++) { int t = sh[k]; sh[k] = acc; acc += t; }
        g_bsum[blockIdx.x] = acc;
    }
    __syncthreads();
    int excl = x - v + sh[wid];
    if (i < n) g_rowptr[i] = excl;
}

// finalize rowptr (+block offset) and compute norm from fixed-point degree
__global__ void k_scanC(int n, int e) {
    __shared__ int s_off;
    int t = threadIdx.x;
    int lane = t & 31;
    if (t < 32) {
        int acc = 0;
        for (int k = lane; k < blockIdx.x; k += 32) acc += g_bsum[k];
        #pragma unroll
        for (int o = 16; o > 0; o >>= 1)
            acc += __shfl_down_sync(0xffffffffu, acc, o);
        if (lane == 0) s_off = acc;
    }
    __syncthreads();
    int i = blockIdx.x * SCAN_B + t;
    if (i < n) {
        g_rowptr[i] += s_off;
        float deg = (float)(g_packed[i] & ((1ull << CNT_SH) - 1)) * (1.0f / FXS);
        g_norm[i] = rsqrtf(fmaxf(deg, 1.0f));
        if (i == 0) g_rowptr[n] = e;
    }
}

// fused: fill CSR (blocks [0, fb), 4 edges/thread) + prep g_ha (blocks [fb,...)).
// Re-zeroes g_packed for the next graph replay.
__global__ void k_prepfill(const float4* __restrict__ h,
                           const int* __restrict__ src,
                           const int* __restrict__ dst,
                           const float* __restrict__ w,
                           int e, int n16, int fb, int T) {
    if (blockIdx.x < fb) {
        int t = blockIdx.x * blockDim.x + threadIdx.x;
        if (t >= T) return;
        #pragma unroll
        for (int k = 0; k < 4; k++) {
            int i = t + k * T;
            if (i < e) {
                int pos = g_rowptr[dst[i]] + (int)g_rank[i];
                g_edge[pos] = make_float2(__int_as_float(src[i]), w[i]);
            }
        }
    } else {
        int idx4 = (blockIdx.x - fb) * blockDim.x + threadIdx.x;
        if (idx4 >= n16) return;
        int node = idx4 >> 4;
        if (idx4 < NN) g_packed[idx4] = 0ull;
        float nm = __ldg(&g_norm[node]);
        float4 v = h[idx4];
        __half2 a = __floats2half2_rn(v.x * nm, v.y * nm);
        __half2 b = __floats2half2_rn(v.z * nm, v.w * nm);
        g_ha[idx4] = make_uint2(*reinterpret_cast<uint32_t*>(&a),
                                *reinterpret_cast<uint32_t*>(&b));
    }
}

// ---------------- gather layers ----------------

// 16 lanes per node; lane sub owns dims [sub*4, sub*4+4) = one uint2 of fp16.
// LAYER=0: read g_ha; g_hb = fp16(sum * norm^2).
// LAYER=1: read g_hb; out = (h0 + hb_own/norm + sum*norm) / 3.
__device__ __forceinline__ void acc4(float* acc, uint2 r, float wt) {
    __half2 p0 = *reinterpret_cast<__half2*>(&r.x);
    __half2 p1 = *reinterpret_cast<__half2*>(&r.y);
    float2 f0 = __half22float2(p0);
    float2 f1 = __half22float2(p1);
    acc[0] += f0.x * wt; acc[1] += f0.y * wt;
    acc[2] += f1.x * wt; acc[3] += f1.y * wt;
}

template <int LAYER>
__global__ void k_gather(const float4* __restrict__ h4,
                         float4* __restrict__ out, int n) {
    const uint2* rows = (LAYER == 0) ? g_ha : g_hb;
    int gid = (blockIdx.x * blockDim.x + threadIdx.x) >> 4;   // node
    int sub = threadIdx.x & 15;
    if (gid >= n) return;
    int beg = g_rowptr[gid];
    int end = g_rowptr[gid + 1];

    float acc[4] = {0.f, 0.f, 0.f, 0.f};
    int j = beg;
    for (; j + 8 <= end; j += 8) {
        float2 e0 = g_edge[j],     e1 = g_edge[j + 1];
        float2 e2 = g_edge[j + 2], e3 = g_edge[j + 3];
        float2 e4 = g_edge[j + 4], e5 = g_edge[j + 5];
        float2 e6 = g_edge[j + 6], e7 = g_edge[j + 7];
        uint2 r0 = rows[(size_t)__float_as_int(e0.x) * 16 + sub];
        uint2 r1 = rows[(size_t)__float_as_int(e1.x) * 16 + sub];
        uint2 r2 = rows[(size_t)__float_as_int(e2.x) * 16 + sub];
        uint2 r3 = rows[(size_t)__float_as_int(e3.x) * 16 + sub];
        uint2 r4 = rows[(size_t)__float_as_int(e4.x) * 16 + sub];
        uint2 r5 = rows[(size_t)__float_as_int(e5.x) * 16 + sub];
        uint2 r6 = rows[(size_t)__float_as_int(e6.x) * 16 + sub];
        uint2 r7 = rows[(size_t)__float_as_int(e7.x) * 16 + sub];
        acc4(acc, r0, e0.y); acc4(acc, r1, e1.y);
        acc4(acc, r2, e2.y); acc4(acc, r3, e3.y);
        acc4(acc, r4, e4.y); acc4(acc, r5, e5.y);
        acc4(acc, r6, e6.y); acc4(acc, r7, e7.y);
    }
    if (j + 4 <= end) {
        float2 e0 = g_edge[j],     e1 = g_edge[j + 1];
        float2 e2 = g_edge[j + 2], e3 = g_edge[j + 3];
        uint2 r0 = rows[(size_t)__float_as_int(e0.x) * 16 + sub];
        uint2 r1 = rows[(size_t)__float_as_int(e1.x) * 16 + sub];
        uint2 r2 = rows[(size_t)__float_as_int(e2.x) * 16 + sub];
        uint2 r3 = rows[(size_t)__float_as_int(e3.x) * 16 + sub];
        acc4(acc, r0, e0.y); acc4(acc, r1, e1.y);
        acc4(acc, r2, e2.y); acc4(acc, r3, e3.y);
        j += 4;
    }
    for (; j < end; ++j) {
        float2 e = g_edge[j];
        uint2 r = rows[(size_t)__float_as_int(e.x) * 16 + sub];
        acc4(acc, r, e.y);
    }

    float nm = g_norm[gid];
    size_t idx = (size_t)gid * 16 + sub;
    if (LAYER == 0) {
        float s = nm * nm;                       // h1*norm = sum*norm^2
        __half2 o0 = __floats2half2_rn(acc[0] * s, acc[1] * s);
        __half2 o1 = __floats2half2_rn(acc[2] * s, acc[3] * s);
        g_hb[idx] = make_uint2(*reinterpret_cast<uint32_t*>(&o0),
                               *reinterpret_cast<uint32_t*>(&o1));
    } else {
        float rin = __frcp_rn(nm);               // 1/norm, norm in (0,1]
        uint2 hb = g_hb[idx];
        __half2 p0 = *reinterpret_cast<__half2*>(&hb.x);
        __half2 p1 = *reinterpret_cast<__half2*>(&hb.y);
        float2 f0 = __half22float2(p0);
        float2 f1 = __half22float2(p1);
        float4 h0 = h4[idx];
        const float third = 1.0f / 3.0f;
        float4 o;
        o.x = (h0.x + f0.x * rin + acc[0] * nm) * third;
        o.y = (h0.y + f0.y * rin + acc[1] * nm) * third;
        o.z = (h0.z + f1.x * rin + acc[2] * nm) * third;
        o.w = (h0.w + f1.y * rin + acc[3] * nm) * third;
        out[idx] = o;
    }
}

extern "C" void kernel_launch(void* const* d_in, const int* in_sizes, int n_in,
                              void* d_out, int out_size) {
    const float* h   = (const float*)d_in[0];
    const float* w   = (const float*)d_in[1];
    const int*   src = (const int*)d_in[2];
    const int*   dst = (const int*)d_in[3];
    float* out = (float*)d_out;

    const int N   = in_sizes[0] / 64;   // 100000
    const int E   = in_sizes[1];        // 1600000
    const int B   = 256;
    const int nb  = (N + SCAN_B - 1) / SCAN_B;   // 391
    const int N16 = N * 16;
    const int T   = (E + 3) / 4;                 // edges per fill stripe
    const int fb  = (T + B - 1) / B;             // fill blocks
    const int pb  = (N16 + B - 1) / B;           // prep blocks

    k_hist    <<<(E + B - 1) / B, B>>>(w, dst, E);
    k_scanA   <<<nb, SCAN_B>>>(N);
    k_scanC   <<<nb, SCAN_B>>>(N, E);
    k_prepfill<<<fb + pb, B>>>((const float4*)h, src, dst, w, E, N16, fb, T);

    const int ggrid = (N * 16 + B - 1) / B;      // 16 lanes per node
    k_gather<0><<<ggrid, B>>>((const float4*)h, (float4*)out, N);
    k_gather<1><<<ggrid, B>>>((const float4*)h, (float4*)out, N);
}